// round 5
// baseline (speedup 1.0000x reference)
#include <cuda_runtime.h>

// Problem constants
#define NB 2048
#define NU 256
#define NM 64

// Output layout: [output (2048*256) | M_key_new (2048*64*256) | M_value_new (2048*64*256)]
#define OUT_O  0
#define OUT_MK (NB*NU)                     // 524288
#define OUT_MV (OUT_MK + NB*NM*NU)         // 34078720

// Scratch (device globals: allocation-free)
__device__ float g_ex[NM * NB];            // exp(scores), [m][b], 512KB
__device__ float g_atsum[NB];              // column sums, 8KB

#define SMEM_FLOATS (2*64*65 + 64)         // 33.6KB shared union

// Copy split between the two launches (rows per tensor)
#define K1_ROWS 1152
#define K2_ROWS (NB - K1_ROWS)             // 896

// Copy one b-row: M_x[b, 1:64, :] -> out[b, 0:63, :]  (63*256 = 16128 floats = 4032 float4)
// Explicit 8-wide batches for MLP.
__device__ __forceinline__ void copy_row(const float* __restrict__ src_base,
                                         float* __restrict__ dst_base, int b) {
    const float4* __restrict__ src =
        reinterpret_cast<const float4*>(src_base + (size_t)b * 16384 + 256);
    float4* __restrict__ dst = reinterpret_cast<float4*>(dst_base + (size_t)b * 16384);
    const int t = threadIdx.x;
    // Batch 1: indices t + i*256, i in [0,8)  -> covers [0,2048)
    {
        float4 v0 = src[t];          float4 v1 = src[t + 256];
        float4 v2 = src[t + 512];    float4 v3 = src[t + 768];
        float4 v4 = src[t + 1024];   float4 v5 = src[t + 1280];
        float4 v6 = src[t + 1536];   float4 v7 = src[t + 1792];
        dst[t] = v0;        dst[t + 256] = v1;
        dst[t + 512] = v2;  dst[t + 768] = v3;
        dst[t + 1024] = v4; dst[t + 1280] = v5;
        dst[t + 1536] = v6; dst[t + 1792] = v7;
    }
    // Batch 2: covers [2048,4032)  (last sub-batch partial: 4032-2048 = 1984 = 7*256+192)
    {
        float4 v0 = src[t + 2048];   float4 v1 = src[t + 2304];
        float4 v2 = src[t + 2560];   float4 v3 = src[t + 2816];
        float4 v4 = src[t + 3072];   float4 v5 = src[t + 3328];
        float4 v6 = src[t + 3584];
        float4 v7;
        bool last = (t + 3840) < 4032;
        if (last) v7 = src[t + 3840];
        dst[t + 2048] = v0; dst[t + 2304] = v1;
        dst[t + 2560] = v2; dst[t + 2816] = v3;
        dst[t + 3072] = v4; dst[t + 3328] = v5;
        dst[t + 3584] = v6;
        if (last) dst[t + 3840] = v7;
    }
}

// ---------------------------------------------------------------------------
// Launch 1: attention scores (exp + column sums) fused with first part of copy
// blocks [0,32): scores for b-tile of 64.  blocks [32, 32+2*K1_ROWS): copy
// ---------------------------------------------------------------------------
__global__ __launch_bounds__(256, 6) void k1_scores_copy(
        const float* __restrict__ inputs,
        const float* __restrict__ M_key,
        const float* __restrict__ M_value,
        float* __restrict__ out) {
    __shared__ float smem[SMEM_FLOATS];
    const int bid = blockIdx.x;
    const int tid = threadIdx.x;

    if (bid < 32) {
        // S[m,b] = sum_k keys0[m,k] * h_t[b,k];  keys0 = M_key[0] (64x256), h_t = inputs[:,256:]
        float (*sk)[65] = reinterpret_cast<float(*)[65]>(smem);            // [k][m]
        float (*sh)[65] = reinterpret_cast<float(*)[65]>(smem + 64 * 65);  // [k][b]
        float* csum = smem + 2 * 64 * 65;

        const int b0 = bid * 64;
        const int tx = tid & 15;   // b micro-group
        const int ty = tid >> 4;   // m micro-group
        float acc[4][4] = {};

        for (int kc = 0; kc < 256; kc += 64) {
            #pragma unroll
            for (int r = 0; r < 16; r++) {
                int e = tid + r * 256;
                int p = e >> 6, q = e & 63;    // p: row (m or b), q: k
                sk[q][p] = M_key[p * 256 + kc + q];
                sh[q][p] = inputs[(b0 + p) * 512 + 256 + kc + q];
            }
            __syncthreads();
            #pragma unroll 8
            for (int k = 0; k < 64; k++) {
                float a[4], h[4];
                #pragma unroll
                for (int i = 0; i < 4; i++) a[i] = sk[k][ty * 4 + i];
                #pragma unroll
                for (int j = 0; j < 4; j++) h[j] = sh[k][tx * 4 + j];
                #pragma unroll
                for (int i = 0; i < 4; i++)
                    #pragma unroll
                    for (int j = 0; j < 4; j++)
                        acc[i][j] = fmaf(a[i], h[j], acc[i][j]);
            }
            __syncthreads();
        }

        if (tid < 64) csum[tid] = 0.0f;
        __syncthreads();

        float cpart[4] = {};
        #pragma unroll
        for (int i = 0; i < 4; i++) {
            #pragma unroll
            for (int j = 0; j < 4; j++) {
                float v = __expf(acc[i][j]);
                g_ex[(ty * 4 + i) * NB + b0 + tx * 4 + j] = v;
                cpart[j] += v;
            }
        }
        #pragma unroll
        for (int j = 0; j < 4; j++) atomicAdd(&csum[tx * 4 + j], cpart[j]);
        __syncthreads();
        if (tid < 64) g_atsum[b0 + tid] = csum[tid];
    } else {
        int cid = bid - 32;                 // [0, 2*K1_ROWS)
        int tensor = cid >= K1_ROWS;
        int b = tensor ? (cid - K1_ROWS) : cid;
        copy_row(tensor ? M_value : M_key,
                 out + (tensor ? OUT_MV : OUT_MK), b);
    }
}

// ---------------------------------------------------------------------------
// Launch 2: new-row GEMMs + attention output + rest of copy
// blocks [0,256):   e_t @ W_{key,value} -> slot 63 of M_*_new (64x64 tiles)
// blocks [256,384): output = at^T @ vals0 with the reference's odd divisor
// blocks [384, 384+2*K2_ROWS): copy b in [K1_ROWS,2048) x {key,value}
// ---------------------------------------------------------------------------
__global__ __launch_bounds__(256, 6) void k2_gemm_out_copy(
        const float* __restrict__ inputs,
        const float* __restrict__ M_key,
        const float* __restrict__ M_value,
        const float* __restrict__ W_key,
        const float* __restrict__ W_value,
        float* __restrict__ out) {
    __shared__ float smem[SMEM_FLOATS];
    const int bid = blockIdx.x;
    const int tid = threadIdx.x;
    const int tx = tid & 15;
    const int ty = tid >> 4;

    if (bid < 256) {
        // m_x[b,u] = sum_k e_t[b,k] * W[k,u];  e_t = inputs[:, :256]
        const int matrix = bid >> 7;            // 0 = key, 1 = value
        const int g2 = bid & 127;
        const int r0 = (g2 >> 2) * 64;          // b tile
        const int c0 = (g2 & 3) * 64;           // u tile
        const float* W = matrix ? W_value : W_key;
        const int obase = matrix ? OUT_MV : OUT_MK;

        float (*sa)[65] = reinterpret_cast<float(*)[65]>(smem);            // [k][b]
        float (*sw)[65] = reinterpret_cast<float(*)[65]>(smem + 64 * 65);  // [k][u]
        float acc[4][4] = {};

        for (int kc = 0; kc < 256; kc += 64) {
            #pragma unroll
            for (int r = 0; r < 16; r++) {
                int e = tid + r * 256;
                int p = e >> 6, q = e & 63;
                sa[q][p] = inputs[(r0 + p) * 512 + kc + q];       // coalesced in q(=k)
                sw[p][q] = W[(kc + p) * 256 + c0 + q];            // coalesced in q(=u)
            }
            __syncthreads();
            #pragma unroll 8
            for (int k = 0; k < 64; k++) {
                float a[4], w[4];
                #pragma unroll
                for (int i = 0; i < 4; i++) a[i] = sa[k][ty * 4 + i];
                #pragma unroll
                for (int j = 0; j < 4; j++) w[j] = sw[k][tx * 4 + j];
                #pragma unroll
                for (int i = 0; i < 4; i++)
                    #pragma unroll
                    for (int j = 0; j < 4; j++)
                        acc[i][j] = fmaf(a[i], w[j], acc[i][j]);
            }
            __syncthreads();
        }
        #pragma unroll
        for (int i = 0; i < 4; i++)
            #pragma unroll
            for (int j = 0; j < 4; j++)
                out[obase + (r0 + ty * 4 + i) * 16384 + 63 * 256 + c0 + tx * 4 + j] = acc[i][j];
    } else if (bid < 384) {
        // output[b,u] = sum_m (ex[m,b] / at_sum[m*32 + b/64]) * vals0[m,u]
        const int gid = bid - 256;
        const int uc = (gid & 3) * 64;          // u tile
        const int bt = gid >> 2;                // b tile index; b0/64 == bt (tile aligned)
        const int b0 = bt * 64;

        float (*sv)[65] = reinterpret_cast<float(*)[65]>(smem);            // [m][u]
        float (*wt)[65] = reinterpret_cast<float(*)[65]>(smem + 64 * 65);  // [m][b]
        float* invs = smem + 2 * 64 * 65;

        if (tid < 64) invs[tid] = 1.0f / g_atsum[tid * 32 + bt];
        __syncthreads();
        #pragma unroll
        for (int r = 0; r < 16; r++) {
            int e = tid + r * 256;
            int p = e >> 6, q = e & 63;        // p = m
            sv[p][q] = M_value[p * 256 + uc + q];
            wt[p][q] = g_ex[p * NB + b0 + q] * invs[p];
        }
        __syncthreads();

        float acc[4][4] = {};                   // i -> b, j -> u
        #pragma unroll 8
        for (int m = 0; m < 64; m++) {
            float a[4], v[4];
            #pragma unroll
            for (int i = 0; i < 4; i++) a[i] = wt[m][ty * 4 + i];
            #pragma unroll
            for (int j = 0; j < 4; j++) v[j] = sv[m][tx * 4 + j];
            #pragma unroll
            for (int i = 0; i < 4; i++)
                #pragma unroll
                for (int j = 0; j < 4; j++)
                    acc[i][j] = fmaf(a[i], v[j], acc[i][j]);
        }
        #pragma unroll
        for (int i = 0; i < 4; i++)
            #pragma unroll
            for (int j = 0; j < 4; j++)
                out[OUT_O + (b0 + ty * 4 + i) * 256 + uc + tx * 4 + j] = acc[i][j];
    } else {
        int cid = bid - 384;                    // [0, 2*K2_ROWS)
        int tensor = cid >= K2_ROWS;
        int b = (tensor ? (cid - K2_ROWS) : cid) + K1_ROWS;
        copy_row(tensor ? M_value : M_key,
                 out + (tensor ? OUT_MV : OUT_MK), b);
    }
}

extern "C" void kernel_launch(void* const* d_in, const int* in_sizes, int n_in,
                              void* d_out, int out_size) {
    const float* inputs  = (const float*)d_in[0];   // (2048, 512)
    const float* M_key   = (const float*)d_in[1];   // (2048, 64, 256)
    const float* M_value = (const float*)d_in[2];   // (2048, 64, 256)
    const float* W_key   = (const float*)d_in[3];   // (256, 256)
    const float* W_value = (const float*)d_in[4];   // (256, 256)
    float* out = (float*)d_out;

    k1_scores_copy<<<32 + 2 * K1_ROWS, 256>>>(inputs, M_key, M_value, out);
    k2_gemm_out_copy<<<384 + 2 * K2_ROWS, 256>>>(inputs, M_key, M_value, W_key, W_value, out);
}

// round 6
// speedup vs baseline: 1.3376x; 1.3376x over previous
#include <cuda_runtime.h>

// Problem constants
#define NB 2048
#define NU 256
#define NM 64

// Output layout: [output (2048*256) | M_key_new (2048*64*256) | M_value_new (2048*64*256)]
#define OUT_O  0
#define OUT_MK (NB*NU)                     // 524288
#define OUT_MV (OUT_MK + NB*NM*NU)         // 34078720

// Scratch (device globals: allocation-free)
__device__ float g_ex[NM * NB];            // exp(scores), [m][b], 512KB
__device__ float g_atsum[NB];              // column sums, 8KB

#define SMEM_FLOATS (2*64*65 + 64)         // 33.6KB shared union

// Copy split between the two launches (rows per tensor)
#define K1_ROWS 1152
#define K2_ROWS (NB - K1_ROWS)             // 896

// Copy one b-row: M_x[b, 1:64, :] -> out[b, 0:63, :]  (63*256 = 16128 floats = 4032 float4)
// 252 threads x 16 float4 each, as two branch-free 8-wide batches (MLP = 8).
__device__ __forceinline__ void copy_row(const float* __restrict__ src_base,
                                         float* __restrict__ dst_base, int b) {
    const int t = threadIdx.x;
    if (t >= 252) return;
    const float4* __restrict__ src =
        reinterpret_cast<const float4*>(src_base + (size_t)b * 16384 + 256);
    float4* __restrict__ dst = reinterpret_cast<float4*>(dst_base + (size_t)b * 16384);
    // Batch 1: j = t + i*252, i in [0,8)
    {
        float4 v0 = src[t];            float4 v1 = src[t + 252];
        float4 v2 = src[t + 504];      float4 v3 = src[t + 756];
        float4 v4 = src[t + 1008];     float4 v5 = src[t + 1260];
        float4 v6 = src[t + 1512];     float4 v7 = src[t + 1764];
        dst[t] = v0;          dst[t + 252] = v1;
        dst[t + 504] = v2;    dst[t + 756] = v3;
        dst[t + 1008] = v4;   dst[t + 1260] = v5;
        dst[t + 1512] = v6;   dst[t + 1764] = v7;
    }
    // Batch 2: j = t + (8+i)*252, i in [0,8)  -> up to t+3780 (< 4032)
    {
        float4 v0 = src[t + 2016];     float4 v1 = src[t + 2268];
        float4 v2 = src[t + 2520];     float4 v3 = src[t + 2772];
        float4 v4 = src[t + 3024];     float4 v5 = src[t + 3276];
        float4 v6 = src[t + 3528];     float4 v7 = src[t + 3780];
        dst[t + 2016] = v0;   dst[t + 2268] = v1;
        dst[t + 2520] = v2;   dst[t + 2772] = v3;
        dst[t + 3024] = v4;   dst[t + 3276] = v5;
        dst[t + 3528] = v6;   dst[t + 3780] = v7;
    }
}

// ---------------------------------------------------------------------------
// Launch 1: attention scores (exp + column sums) fused with first part of copy
// blocks [0,32): scores for b-tile of 64.  blocks [32, 32+2*K1_ROWS): copy
// ---------------------------------------------------------------------------
__global__ __launch_bounds__(256, 4) void k1_scores_copy(
        const float* __restrict__ inputs,
        const float* __restrict__ M_key,
        const float* __restrict__ M_value,
        float* __restrict__ out) {
    __shared__ float smem[SMEM_FLOATS];
    const int bid = blockIdx.x;
    const int tid = threadIdx.x;

    if (bid < 32) {
        // S[m,b] = sum_k keys0[m,k] * h_t[b,k];  keys0 = M_key[0] (64x256), h_t = inputs[:,256:]
        float (*sk)[65] = reinterpret_cast<float(*)[65]>(smem);            // [k][m]
        float (*sh)[65] = reinterpret_cast<float(*)[65]>(smem + 64 * 65);  // [k][b]
        float* csum = smem + 2 * 64 * 65;

        const int b0 = bid * 64;
        const int tx = tid & 15;   // b micro-group
        const int ty = tid >> 4;   // m micro-group
        float acc[4][4] = {};

        for (int kc = 0; kc < 256; kc += 64) {
            #pragma unroll
            for (int r = 0; r < 16; r++) {
                int e = tid + r * 256;
                int p = e >> 6, q = e & 63;    // p: row (m or b), q: k
                sk[q][p] = M_key[p * 256 + kc + q];
                sh[q][p] = inputs[(b0 + p) * 512 + 256 + kc + q];
            }
            __syncthreads();
            #pragma unroll 8
            for (int k = 0; k < 64; k++) {
                float a[4], h[4];
                #pragma unroll
                for (int i = 0; i < 4; i++) a[i] = sk[k][ty * 4 + i];
                #pragma unroll
                for (int j = 0; j < 4; j++) h[j] = sh[k][tx * 4 + j];
                #pragma unroll
                for (int i = 0; i < 4; i++)
                    #pragma unroll
                    for (int j = 0; j < 4; j++)
                        acc[i][j] = fmaf(a[i], h[j], acc[i][j]);
            }
            __syncthreads();
        }

        if (tid < 64) csum[tid] = 0.0f;
        __syncthreads();

        float cpart[4] = {};
        #pragma unroll
        for (int i = 0; i < 4; i++) {
            #pragma unroll
            for (int j = 0; j < 4; j++) {
                float v = __expf(acc[i][j]);
                g_ex[(ty * 4 + i) * NB + b0 + tx * 4 + j] = v;
                cpart[j] += v;
            }
        }
        #pragma unroll
        for (int j = 0; j < 4; j++) atomicAdd(&csum[tx * 4 + j], cpart[j]);
        __syncthreads();
        if (tid < 64) g_atsum[b0 + tid] = csum[tid];
    } else {
        int cid = bid - 32;                 // [0, 2*K1_ROWS)
        int tensor = cid >= K1_ROWS;
        int b = tensor ? (cid - K1_ROWS) : cid;
        copy_row(tensor ? M_value : M_key,
                 out + (tensor ? OUT_MV : OUT_MK), b);
    }
}

// ---------------------------------------------------------------------------
// Launch 2: new-row GEMMs + attention output + rest of copy
// blocks [0,256):   e_t @ W_{key,value} -> slot 63 of M_*_new (64x64 tiles)
// blocks [256,384): output = at^T @ vals0 with the reference's odd divisor
// blocks [384, 384+2*K2_ROWS): copy b in [K1_ROWS,2048) x {key,value}
// ---------------------------------------------------------------------------
__global__ __launch_bounds__(256, 4) void k2_gemm_out_copy(
        const float* __restrict__ inputs,
        const float* __restrict__ M_key,
        const float* __restrict__ M_value,
        const float* __restrict__ W_key,
        const float* __restrict__ W_value,
        float* __restrict__ out) {
    __shared__ float smem[SMEM_FLOATS];
    const int bid = blockIdx.x;
    const int tid = threadIdx.x;
    const int tx = tid & 15;
    const int ty = tid >> 4;

    if (bid < 256) {
        // m_x[b,u] = sum_k e_t[b,k] * W[k,u];  e_t = inputs[:, :256]
        const int matrix = bid >> 7;            // 0 = key, 1 = value
        const int g2 = bid & 127;
        const int r0 = (g2 >> 2) * 64;          // b tile
        const int c0 = (g2 & 3) * 64;           // u tile
        const float* W = matrix ? W_value : W_key;
        const int obase = matrix ? OUT_MV : OUT_MK;

        float (*sa)[65] = reinterpret_cast<float(*)[65]>(smem);            // [k][b]
        float (*sw)[65] = reinterpret_cast<float(*)[65]>(smem + 64 * 65);  // [k][u]
        float acc[4][4] = {};

        for (int kc = 0; kc < 256; kc += 64) {
            #pragma unroll
            for (int r = 0; r < 16; r++) {
                int e = tid + r * 256;
                int p = e >> 6, q = e & 63;
                sa[q][p] = inputs[(r0 + p) * 512 + kc + q];       // coalesced in q(=k)
                sw[p][q] = W[(kc + p) * 256 + c0 + q];            // coalesced in q(=u)
            }
            __syncthreads();
            #pragma unroll 8
            for (int k = 0; k < 64; k++) {
                float a[4], w[4];
                #pragma unroll
                for (int i = 0; i < 4; i++) a[i] = sa[k][ty * 4 + i];
                #pragma unroll
                for (int j = 0; j < 4; j++) w[j] = sw[k][tx * 4 + j];
                #pragma unroll
                for (int i = 0; i < 4; i++)
                    #pragma unroll
                    for (int j = 0; j < 4; j++)
                        acc[i][j] = fmaf(a[i], w[j], acc[i][j]);
            }
            __syncthreads();
        }
        #pragma unroll
        for (int i = 0; i < 4; i++)
            #pragma unroll
            for (int j = 0; j < 4; j++)
                out[obase + (r0 + ty * 4 + i) * 16384 + 63 * 256 + c0 + tx * 4 + j] = acc[i][j];
    } else if (bid < 384) {
        // output[b,u] = sum_m (ex[m,b] / at_sum[m*32 + b/64]) * vals0[m,u]
        const int gid = bid - 256;
        const int uc = (gid & 3) * 64;          // u tile
        const int bt = gid >> 2;                // b tile index; b0/64 == bt (tile aligned)
        const int b0 = bt * 64;

        float (*sv)[65] = reinterpret_cast<float(*)[65]>(smem);            // [m][u]
        float (*wt)[65] = reinterpret_cast<float(*)[65]>(smem + 64 * 65);  // [m][b]
        float* invs = smem + 2 * 64 * 65;

        if (tid < 64) invs[tid] = 1.0f / g_atsum[tid * 32 + bt];
        __syncthreads();
        #pragma unroll
        for (int r = 0; r < 16; r++) {
            int e = tid + r * 256;
            int p = e >> 6, q = e & 63;        // p = m
            sv[p][q] = M_value[p * 256 + uc + q];
            wt[p][q] = g_ex[p * NB + b0 + q] * invs[p];
        }
        __syncthreads();

        float acc[4][4] = {};                   // i -> b, j -> u
        #pragma unroll 8
        for (int m = 0; m < 64; m++) {
            float a[4], v[4];
            #pragma unroll
            for (int i = 0; i < 4; i++) a[i] = wt[m][ty * 4 + i];
            #pragma unroll
            for (int j = 0; j < 4; j++) v[j] = sv[m][tx * 4 + j];
            #pragma unroll
            for (int i = 0; i < 4; i++)
                #pragma unroll
                for (int j = 0; j < 4; j++)
                    acc[i][j] = fmaf(a[i], v[j], acc[i][j]);
        }
        #pragma unroll
        for (int i = 0; i < 4; i++)
            #pragma unroll
            for (int j = 0; j < 4; j++)
                out[OUT_O + (b0 + ty * 4 + i) * 256 + uc + tx * 4 + j] = acc[i][j];
    } else {
        int cid = bid - 384;                    // [0, 2*K2_ROWS)
        int tensor = cid >= K2_ROWS;
        int b = (tensor ? (cid - K2_ROWS) : cid) + K1_ROWS;
        copy_row(tensor ? M_value : M_key,
                 out + (tensor ? OUT_MV : OUT_MK), b);
    }
}

extern "C" void kernel_launch(void* const* d_in, const int* in_sizes, int n_in,
                              void* d_out, int out_size) {
    const float* inputs  = (const float*)d_in[0];   // (2048, 512)
    const float* M_key   = (const float*)d_in[1];   // (2048, 64, 256)
    const float* M_value = (const float*)d_in[2];   // (2048, 64, 256)
    const float* W_key   = (const float*)d_in[3];   // (256, 256)
    const float* W_value = (const float*)d_in[4];   // (256, 256)
    float* out = (float*)d_out;

    k1_scores_copy<<<32 + 2 * K1_ROWS, 256>>>(inputs, M_key, M_value, out);
    k2_gemm_out_copy<<<384 + 2 * K2_ROWS, 256>>>(inputs, M_key, M_value, W_key, W_value, out);
}

// round 13
// speedup vs baseline: 1.5822x; 1.1828x over previous
#include <cuda_runtime.h>

// Problem constants
#define NB 2048
#define NU 256
#define NM 64

// Output layout: [output (2048*256) | M_key_new (2048*64*256) | M_value_new (2048*64*256)]
#define OUT_O  0
#define OUT_MK (NB*NU)                     // 524288
#define OUT_MV (OUT_MK + NB*NM*NU)         // 34078720

// Scratch (device globals: allocation-free)
__device__ float g_ex[NM * NB];            // exp(scores), [m][b], 512KB
__device__ float g_atsum[NB];              // column sums, 8KB

#define SMEM_FLOATS (2*64*65 + 64)         // 33.6KB shared union

// Copy split between the two launches (rows per tensor)
#define K1_ROWS 1088
#define K2_ROWS (NB - K1_ROWS)             // 960

// Copy one b-row: M_x[b, 1:64, :] -> out[b, 0:63, :]  (63*256 = 16128 floats = 4032 float4)
// Stride-256 (warp segments stay 128B-aligned), two 8-deep batches, streaming hints.
__device__ __forceinline__ void copy_row(const float* __restrict__ src_base,
                                         float* __restrict__ dst_base, int b) {
    const int t = threadIdx.x;
    const float4* __restrict__ src =
        reinterpret_cast<const float4*>(src_base + (size_t)b * 16384 + 256);
    float4* __restrict__ dst = reinterpret_cast<float4*>(dst_base + (size_t)b * 16384);
    // Batch 1: i = 0..7 (all full)
    {
        float4 v0 = __ldcs(&src[t]);          float4 v1 = __ldcs(&src[t + 256]);
        float4 v2 = __ldcs(&src[t + 512]);    float4 v3 = __ldcs(&src[t + 768]);
        float4 v4 = __ldcs(&src[t + 1024]);   float4 v5 = __ldcs(&src[t + 1280]);
        float4 v6 = __ldcs(&src[t + 1536]);   float4 v7 = __ldcs(&src[t + 1792]);
        __stcs(&dst[t],        v0);  __stcs(&dst[t + 256],  v1);
        __stcs(&dst[t + 512],  v2);  __stcs(&dst[t + 768],  v3);
        __stcs(&dst[t + 1024], v4);  __stcs(&dst[t + 1280], v5);
        __stcs(&dst[t + 1536], v6);  __stcs(&dst[t + 1792], v7);
    }
    // Batch 2: i = 8..14 full, i = 15 predicated (4032 - 3840 = 192)
    {
        const bool last = t < 192;
        float4 v0 = __ldcs(&src[t + 2048]);   float4 v1 = __ldcs(&src[t + 2304]);
        float4 v2 = __ldcs(&src[t + 2560]);   float4 v3 = __ldcs(&src[t + 2816]);
        float4 v4 = __ldcs(&src[t + 3072]);   float4 v5 = __ldcs(&src[t + 3328]);
        float4 v6 = __ldcs(&src[t + 3584]);
        float4 v7;
        if (last) v7 = __ldcs(&src[t + 3840]);
        __stcs(&dst[t + 2048], v0);  __stcs(&dst[t + 2304], v1);
        __stcs(&dst[t + 2560], v2);  __stcs(&dst[t + 2816], v3);
        __stcs(&dst[t + 3072], v4);  __stcs(&dst[t + 3328], v5);
        __stcs(&dst[t + 3584], v6);
        if (last) __stcs(&dst[t + 3840], v7);
    }
}

// ---------------------------------------------------------------------------
// Launch 1: attention scores (exp + column sums) fused with first part of copy
// blocks [0,32): scores for b-tile of 64.  blocks [32, 32+2*K1_ROWS): copy
// ---------------------------------------------------------------------------
__global__ __launch_bounds__(256) void k1_scores_copy(
        const float* __restrict__ inputs,
        const float* __restrict__ M_key,
        const float* __restrict__ M_value,
        float* __restrict__ out) {
    __shared__ float smem[SMEM_FLOATS];
    const int bid = blockIdx.x;
    const int tid = threadIdx.x;

    if (bid < 32) {
        // S[m,b] = sum_k keys0[m,k] * h_t[b,k];  keys0 = M_key[0] (64x256), h_t = inputs[:,256:]
        float (*sk)[65] = reinterpret_cast<float(*)[65]>(smem);            // [k][m]
        float (*sh)[65] = reinterpret_cast<float(*)[65]>(smem + 64 * 65);  // [k][b]
        float* csum = smem + 2 * 64 * 65;

        const int b0 = bid * 64;
        const int tx = tid & 15;   // b micro-group
        const int ty = tid >> 4;   // m micro-group
        float acc[4][4] = {};

        for (int kc = 0; kc < 256; kc += 64) {
            #pragma unroll
            for (int r = 0; r < 16; r++) {
                int e = tid + r * 256;
                int p = e >> 6, q = e & 63;    // p: row (m or b), q: k
                sk[q][p] = M_key[p * 256 + kc + q];
                sh[q][p] = inputs[(b0 + p) * 512 + 256 + kc + q];
            }
            __syncthreads();
            #pragma unroll 8
            for (int k = 0; k < 64; k++) {
                float a[4], h[4];
                #pragma unroll
                for (int i = 0; i < 4; i++) a[i] = sk[k][ty * 4 + i];
                #pragma unroll
                for (int j = 0; j < 4; j++) h[j] = sh[k][tx * 4 + j];
                #pragma unroll
                for (int i = 0; i < 4; i++)
                    #pragma unroll
                    for (int j = 0; j < 4; j++)
                        acc[i][j] = fmaf(a[i], h[j], acc[i][j]);
            }
            __syncthreads();
        }

        if (tid < 64) csum[tid] = 0.0f;
        __syncthreads();

        float cpart[4] = {};
        #pragma unroll
        for (int i = 0; i < 4; i++) {
            #pragma unroll
            for (int j = 0; j < 4; j++) {
                float v = __expf(acc[i][j]);
                g_ex[(ty * 4 + i) * NB + b0 + tx * 4 + j] = v;
                cpart[j] += v;
            }
        }
        #pragma unroll
        for (int j = 0; j < 4; j++) atomicAdd(&csum[tx * 4 + j], cpart[j]);
        __syncthreads();
        if (tid < 64) g_atsum[b0 + tid] = csum[tid];
    } else {
        int cid = bid - 32;                 // [0, 2*K1_ROWS)
        int tensor = cid >= K1_ROWS;
        int b = tensor ? (cid - K1_ROWS) : cid;
        copy_row(tensor ? M_value : M_key,
                 out + (tensor ? OUT_MV : OUT_MK), b);
    }
}

// ---------------------------------------------------------------------------
// Launch 2: new-row GEMMs + attention output + rest of copy
// blocks [0,256):   e_t @ W_{key,value} -> slot 63 of M_*_new (64x64 tiles)
// blocks [256,384): output = at^T @ vals0 with the reference's odd divisor
// blocks [384, 384+2*K2_ROWS): copy b in [K1_ROWS,2048) x {key,value}
// ---------------------------------------------------------------------------
__global__ __launch_bounds__(256) void k2_gemm_out_copy(
        const float* __restrict__ inputs,
        const float* __restrict__ M_key,
        const float* __restrict__ M_value,
        const float* __restrict__ W_key,
        const float* __restrict__ W_value,
        float* __restrict__ out) {
    __shared__ float smem[SMEM_FLOATS];
    const int bid = blockIdx.x;
    const int tid = threadIdx.x;
    const int tx = tid & 15;
    const int ty = tid >> 4;

    if (bid < 256) {
        // m_x[b,u] = sum_k e_t[b,k] * W[k,u];  e_t = inputs[:, :256]
        const int matrix = bid >> 7;            // 0 = key, 1 = value
        const int g2 = bid & 127;
        const int r0 = (g2 >> 2) * 64;          // b tile
        const int c0 = (g2 & 3) * 64;           // u tile
        const float* W = matrix ? W_value : W_key;
        const int obase = matrix ? OUT_MV : OUT_MK;

        float (*sa)[65] = reinterpret_cast<float(*)[65]>(smem);            // [k][b]
        float (*sw)[65] = reinterpret_cast<float(*)[65]>(smem + 64 * 65);  // [k][u]
        float acc[4][4] = {};

        for (int kc = 0; kc < 256; kc += 64) {
            #pragma unroll
            for (int r = 0; r < 16; r++) {
                int e = tid + r * 256;
                int p = e >> 6, q = e & 63;
                sa[q][p] = inputs[(r0 + p) * 512 + kc + q];       // coalesced in q(=k)
                sw[p][q] = W[(kc + p) * 256 + c0 + q];            // coalesced in q(=u)
            }
            __syncthreads();
            #pragma unroll 8
            for (int k = 0; k < 64; k++) {
                float a[4], w[4];
                #pragma unroll
                for (int i = 0; i < 4; i++) a[i] = sa[k][ty * 4 + i];
                #pragma unroll
                for (int j = 0; j < 4; j++) w[j] = sw[k][tx * 4 + j];
                #pragma unroll
                for (int i = 0; i < 4; i++)
                    #pragma unroll
                    for (int j = 0; j < 4; j++)
                        acc[i][j] = fmaf(a[i], w[j], acc[i][j]);
            }
            __syncthreads();
        }
        #pragma unroll
        for (int i = 0; i < 4; i++)
            #pragma unroll
            for (int j = 0; j < 4; j++)
                out[obase + (r0 + ty * 4 + i) * 16384 + 63 * 256 + c0 + tx * 4 + j] = acc[i][j];
    } else if (bid < 384) {
        // output[b,u] = sum_m (ex[m,b] / at_sum[m*32 + b/64]) * vals0[m,u]
        const int gid = bid - 256;
        const int uc = (gid & 3) * 64;          // u tile
        const int bt = gid >> 2;                // b tile index; b0/64 == bt (tile aligned)
        const int b0 = bt * 64;

        float (*sv)[65] = reinterpret_cast<float(*)[65]>(smem);            // [m][u]
        float (*wt)[65] = reinterpret_cast<float(*)[65]>(smem + 64 * 65);  // [m][b]
        float* invs = smem + 2 * 64 * 65;

        if (tid < 64) invs[tid] = 1.0f / g_atsum[tid * 32 + bt];
        __syncthreads();
        #pragma unroll
        for (int r = 0; r < 16; r++) {
            int e = tid + r * 256;
            int p = e >> 6, q = e & 63;        // p = m
            sv[p][q] = M_value[p * 256 + uc + q];
            wt[p][q] = g_ex[p * NB + b0 + q] * invs[p];
        }
        __syncthreads();

        float acc[4][4] = {};                   // i -> b, j -> u
        #pragma unroll 8
        for (int m = 0; m < 64; m++) {
            float a[4], v[4];
            #pragma unroll
            for (int i = 0; i < 4; i++) a[i] = wt[m][ty * 4 + i];
            #pragma unroll
            for (int j = 0; j < 4; j++) v[j] = sv[m][tx * 4 + j];
            #pragma unroll
            for (int i = 0; i < 4; i++)
                #pragma unroll
                for (int j = 0; j < 4; j++)
                    acc[i][j] = fmaf(a[i], v[j], acc[i][j]);
        }
        #pragma unroll
        for (int i = 0; i < 4; i++)
            #pragma unroll
            for (int j = 0; j < 4; j++)
                out[OUT_O + (b0 + ty * 4 + i) * 256 + uc + tx * 4 + j] = acc[i][j];
    } else {
        int cid = bid - 384;                    // [0, 2*K2_ROWS)
        int tensor = cid >= K2_ROWS;
        int b = (tensor ? (cid - K2_ROWS) : cid) + K1_ROWS;
        copy_row(tensor ? M_value : M_key,
                 out + (tensor ? OUT_MV : OUT_MK), b);
    }
}

extern "C" void kernel_launch(void* const* d_in, const int* in_sizes, int n_in,
                              void* d_out, int out_size) {
    const float* inputs  = (const float*)d_in[0];   // (2048, 512)
    const float* M_key   = (const float*)d_in[1];   // (2048, 64, 256)
    const float* M_value = (const float*)d_in[2];   // (2048, 64, 256)
    const float* W_key   = (const float*)d_in[3];   // (256, 256)
    const float* W_value = (const float*)d_in[4];   // (256, 256)
    float* out = (float*)d_out;

    k1_scores_copy<<<32 + 2 * K1_ROWS, 256>>>(inputs, M_key, M_value, out);
    k2_gemm_out_copy<<<384 + 2 * K2_ROWS, 256>>>(inputs, M_key, M_value, W_key, W_value, out);
}